// round 5
// baseline (speedup 1.0000x reference)
#include <cuda_runtime.h>
#include <cuda_fp16.h>
#include <cstdint>

// ---------------- problem constants ----------------
#define BB 8
#define NN 2048
#define CIN 64
#define NK 32
#define KDIM 4096
#define KD2  (KDIM/2)
#define NPTS (BB*NN)
#define COUT 128
#define TRIG_N 2048
#define TWO_PI 6.283185307179586f

// ---------------- device scratch (static, no allocs) ----------------
__device__ __half   g_Ah[(size_t)NPTS * KDIM];      // 128 MB, [p][k] fp16, k-pairs packed
__device__ float    g_featT[(size_t)BB * NN * CIN]; // feature transposed [b][n][c]
__device__ float    g_xT[(size_t)BB * NN * 3];      // coords transposed [b][n][d]
__device__ unsigned g_cwP[(size_t)KD2 * COUT];      // [k2][o] half2(w[o][2k2], w[o][2k2+1])
__device__ float2   g_trig[TRIG_N];                 // (sin, cos)(2*pi*i/TRIG_N)

__device__ __forceinline__ unsigned pack2(float lo, float hi) {
    __half2 h = __floats2half2_rn(lo, hi);
    return *reinterpret_cast<unsigned*>(&h);
}

// table-based sincos: x given in TURNS (arg/2pi). err <= (pi/TRIG_N)^2/2 ~ 5e-6
__device__ __forceinline__ void sincos_turns(float t, float& s, float& c) {
    float fr = t - floorf(t);                 // [0,1)
    float fi = fr * (float)TRIG_N;
    int idx = (int)fi;
    idx &= (TRIG_N - 1);
    float dx = (fi - (float)idx) * (TWO_PI / (float)TRIG_N);
    float2 sc = __ldg(&g_trig[idx]);
    s = fmaf(dx, sc.y, sc.x);                 // sin ~ s0 + dx*c0
    c = fmaf(-dx, sc.x, sc.y);                // cos ~ c0 - dx*s0
}

// m16n8k16 fp16 mma, f32 accumulate
__device__ __forceinline__ void mma_f16(float& c0, float& c1, float& c2, float& c3,
                                        unsigned a0, unsigned a1, unsigned a2, unsigned a3,
                                        unsigned b0, unsigned b1) {
    asm volatile(
        "mma.sync.aligned.m16n8k16.row.col.f32.f16.f16.f32 "
        "{%0,%1,%2,%3},{%4,%5,%6,%7},{%8,%9},{%0,%1,%2,%3};"
        : "+f"(c0), "+f"(c1), "+f"(c2), "+f"(c3)
        : "r"(a0), "r"(a1), "r"(a2), "r"(a3), "r"(b0), "r"(b1));
}

// ---------------- kernel 0: transposes + weight packing + trig table ----------------
__global__ void prep_kernel(const float* __restrict__ x,
                            const float* __restrict__ feat,
                            const float* __restrict__ cw) {
    const int stride = gridDim.x * blockDim.x;
    const int tid = blockIdx.x * blockDim.x + threadIdx.x;

    for (int e = tid; e < TRIG_N; e += stride) {
        float s, c;
        sincosf(TWO_PI * (float)e / (float)TRIG_N, &s, &c);
        g_trig[e] = make_float2(s, c);
    }
    for (int e = tid; e < BB * CIN * NN; e += stride) {
        int b = e / (CIN * NN);
        int r = e - b * (CIN * NN);
        int c = r / NN;
        int n = r - c * NN;
        g_featT[((size_t)b * NN + n) * CIN + c] = feat[e];
    }
    for (int e = tid; e < BB * 3 * NN; e += stride) {
        int b = e / (3 * NN);
        int r = e - b * (3 * NN);
        int d = r / NN;
        int n = r - d * NN;
        g_xT[((size_t)b * NN + n) * 3 + d] = x[e];
    }
    // conv_w [O=128][K=4096] -> g_cwP[k2][o] packed half2 along k
    for (int e = tid; e < COUT * KD2; e += stride) {
        int o  = e >> 11;
        int k2 = e & (KD2 - 1);
        float2 v = *reinterpret_cast<const float2*>(cw + (size_t)o * KDIM + 2 * k2);
        g_cwP[(size_t)k2 * COUT + o] = pack2(v.x, v.y);
    }
}

// ---------------- kernel 1: per-point fp16 tensor-core MLP + F@perm ----------------
__global__ __launch_bounds__(128, 8) void point_kernel(
    const int*   __restrict__ nidx,
    const float* __restrict__ Brff,   // [7,32]
    const float* __restrict__ kern,   // [3,32]
    const float* __restrict__ mw,     // [64,64]
    const float* __restrict__ mb)     // [64]
{
    const int p = blockIdx.x;
    const int b = p >> 11;
    const int t = threadIdx.x;
    const int lane = t & 31;
    const int w = t >> 5;
    const int grp = lane >> 2;
    const int tig = lane & 3;

    __shared__ unsigned u_xf[32][36];  // [k][m2]: m pairs, m<32 sin block, m>=32 cos block
    __shared__ unsigned u_F[128][20];  // [shuffled ch][k2]
    __shared__ unsigned u_pT[32][20];  // [j][i2]: perm^T
    __shared__ float s_br[7][32];
    __shared__ float s_rel[32][3];
    __shared__ float s_dis[32];
    __shared__ float s_c0[3];
    __shared__ int   s_idx[32];

    // constant A fragments for GEMM1 (mw rows [16w,16w+16)), fp16 packed
    unsigned amw[4][4];
    {
        const int r0 = w * 16 + grp;
        #pragma unroll
        for (int ks = 0; ks < 4; ks++) {
            const int m0 = ks * 16 + 2 * tig;
            float2 v0 = *reinterpret_cast<const float2*>(mw + r0 * 64 + m0);
            float2 v1 = *reinterpret_cast<const float2*>(mw + (r0 + 8) * 64 + m0);
            float2 v2 = *reinterpret_cast<const float2*>(mw + r0 * 64 + m0 + 8);
            float2 v3 = *reinterpret_cast<const float2*>(mw + (r0 + 8) * 64 + m0 + 8);
            amw[ks][0] = pack2(v0.x, v0.y);
            amw[ks][1] = pack2(v1.x, v1.y);
            amw[ks][2] = pack2(v2.x, v2.y);
            amw[ks][3] = pack2(v3.x, v3.y);
        }
    }
    const float bv0 = mb[w * 16 + grp];
    const float bv1 = mb[w * 16 + grp + 8];

    for (int e = t; e < 224; e += 128) s_br[e >> 5][e & 31] = Brff[e];
    if (t < 32) s_idx[t] = nidx[p * NK + t];
    __syncthreads();

    float cx = 0.f, cy = 0.f, cz = 0.f;
    if (t < 32) {
        const float* cp = g_xT + ((size_t)b * NN + s_idx[t]) * 3;
        cx = cp[0]; cy = cp[1]; cz = cp[2];
    }

    // feature gather -> u_F rows 0,1 mod 4 (shuffled), packed neighbor pairs
    #pragma unroll
    for (int it = 0; it < 8; it++) {
        int e = t + it * 128;
        int c = e & 63, k2 = e >> 6;
        float f0 = g_featT[((size_t)b * NN + s_idx[2 * k2])     * CIN + c];
        float f1 = g_featT[((size_t)b * NN + s_idx[2 * k2 + 1]) * CIN + c];
        u_F[(c & 31) * 4 + (c >> 5)][k2] = pack2(f0, f1);
    }

    if (t < 32) {
        float c0x = __shfl_sync(0xffffffffu, cx, 0);
        float c0y = __shfl_sync(0xffffffffu, cy, 0);
        float c0z = __shfl_sync(0xffffffffu, cz, 0);
        float rx = cx - c0x, ry = cy - c0y, rz = cz - c0z;
        s_rel[t][0] = rx; s_rel[t][1] = ry; s_rel[t][2] = rz;
        s_dis[t] = sqrtf(rx * rx + ry * ry + rz * rz);
        if (t == 0) { s_c0[0] = c0x; s_c0[1] = c0y; s_c0[2] = c0z; }
    }
    __syncthreads();

    // ---- RFF via table sincos: args computed in TURNS (no 2*pi factor) ----
    const float c0x = s_c0[0], c0y = s_c0[1], c0z = s_c0[2];
    #pragma unroll
    for (int it = 0; it < 4; it++) {
        int e = t + it * 128;
        int k = e >> 4, m2 = e & 15;
        float rx = s_rel[k][0], ry = s_rel[k][1], rz = s_rel[k][2], dd = s_dis[k];
        int m = 2 * m2;
        float t0 = c0x * s_br[0][m] + c0y * s_br[1][m] + c0z * s_br[2][m]
                 + rx * s_br[3][m] + ry * s_br[4][m] + rz * s_br[5][m]
                 + dd * s_br[6][m];
        float t1 = c0x * s_br[0][m+1] + c0y * s_br[1][m+1] + c0z * s_br[2][m+1]
                 + rx * s_br[3][m+1] + ry * s_br[4][m+1] + rz * s_br[5][m+1]
                 + dd * s_br[6][m+1];
        float s0, cv0, s1, cv1;
        sincos_turns(t0, s0, cv0);
        sincos_turns(t1, s1, cv1);
        u_xf[k][m2]      = pack2(s0, s1);
        u_xf[k][16 + m2] = pack2(cv0, cv1);
    }

    // ---- perm + topkmax, one column per thread, 3 recompute passes ----
    if (t < 32) {
        const int j = t;
        const float kx = kern[j], ky = kern[32 + j], kz = kern[64 + j];
        float s1 = 0.f;
        #pragma unroll
        for (int i = 0; i < 32; i++) {
            float v = s_rel[i][0] * kx + s_rel[i][1] * ky + s_rel[i][2] * kz;
            if (i == 0 && j == 0) v += 1.0f;
            s1 += fmaxf(v, 0.f);
        }
        float r1 = 1.0f / (s1 + 1e-6f);
        float s2 = 0.f;
        #pragma unroll
        for (int i = 0; i < 32; i++) {
            float v = s_rel[i][0] * kx + s_rel[i][1] * ky + s_rel[i][2] * kz;
            if (i == 0 && j == 0) v += 1.0f;
            v = fmaxf(v, 0.f) * r1;
            s2 += v * v;
        }
        float r2 = 1.0f / (s2 + 1e-6f);
        #pragma unroll
        for (int i2 = 0; i2 < 16; i2++) {
            float w0, w1;
            {
                int i = 2 * i2;
                float v = s_rel[i][0] * kx + s_rel[i][1] * ky + s_rel[i][2] * kz;
                if (i == 0 && j == 0) v += 1.0f;
                v = fmaxf(v, 0.f) * r1;
                v = v * v * r2;
                w0 = (v > 0.1f) ? v : 0.0f;
            }
            {
                int i = 2 * i2 + 1;
                float v = s_rel[i][0] * kx + s_rel[i][1] * ky + s_rel[i][2] * kz;
                v = fmaxf(v, 0.f) * r1;
                v = v * v * r2;
                w1 = (v > 0.1f) ? v : 0.0f;
            }
            u_pT[j][i2] = pack2(w0, w1);
        }
    }
    __syncthreads();

    // ---- GEMM1: mlp out rows [16w,16w+16), bias in accumulator ----
    {
        float acc[4][4];
        #pragma unroll
        for (int nt = 0; nt < 4; nt++) {
            acc[nt][0] = bv0; acc[nt][1] = bv0;
            acc[nt][2] = bv1; acc[nt][3] = bv1;
        }
        #pragma unroll
        for (int ks = 0; ks < 4; ks++) {
            const int kb = ks * 8;
            #pragma unroll
            for (int nt = 0; nt < 4; nt++) {
                unsigned b0 = u_xf[nt * 8 + grp][kb + tig];
                unsigned b1 = u_xf[nt * 8 + grp][kb + tig + 4];
                mma_f16(acc[nt][0], acc[nt][1], acc[nt][2], acc[nt][3],
                        amw[ks][0], amw[ks][1], amw[ks][2], amw[ks][3], b0, b1);
            }
        }
        const int r0 = w * 16 + grp, r1 = r0 + 8;
        const int cs0 = (r0 & 31) * 4 + 2 + (r0 >> 5);
        const int cs1 = (r1 & 31) * 4 + 2 + (r1 >> 5);
        #pragma unroll
        for (int nt = 0; nt < 4; nt++) {
            u_F[cs0][nt * 4 + tig] = pack2(acc[nt][0], acc[nt][1]);
            u_F[cs1][nt * 4 + tig] = pack2(acc[nt][2], acc[nt][3]);
        }
    }
    __syncthreads();

    // ---- GEMM2: feats2 = F @ perm, rows [32w, 32w+32) ----
    {
        float acc[2][4][4];
        #pragma unroll
        for (int mt = 0; mt < 2; mt++)
            #pragma unroll
            for (int nt = 0; nt < 4; nt++)
                #pragma unroll
                for (int r = 0; r < 4; r++) acc[mt][nt][r] = 0.f;

        #pragma unroll
        for (int ks = 0; ks < 2; ks++) {
            const int kb = ks * 8;
            unsigned a[2][4];
            #pragma unroll
            for (int mt = 0; mt < 2; mt++) {
                const int rb = w * 32 + mt * 16;
                a[mt][0] = u_F[rb + grp][kb + tig];
                a[mt][1] = u_F[rb + grp + 8][kb + tig];
                a[mt][2] = u_F[rb + grp][kb + tig + 4];
                a[mt][3] = u_F[rb + grp + 8][kb + tig + 4];
            }
            #pragma unroll
            for (int nt = 0; nt < 4; nt++) {
                unsigned b0 = u_pT[nt * 8 + grp][kb + tig];
                unsigned b1 = u_pT[nt * 8 + grp][kb + tig + 4];
                #pragma unroll
                for (int mt = 0; mt < 2; mt++)
                    mma_f16(acc[mt][nt][0], acc[mt][nt][1], acc[mt][nt][2], acc[mt][nt][3],
                            a[mt][0], a[mt][1], a[mt][2], a[mt][3], b0, b1);
            }
        }

        unsigned* Ap = reinterpret_cast<unsigned*>(g_Ah + (size_t)p * KDIM);
        #pragma unroll
        for (int mt = 0; mt < 2; mt++) {
            const int r = w * 32 + mt * 16 + grp;
            #pragma unroll
            for (int nt = 0; nt < 4; nt++) {
                Ap[r * 16 + nt * 4 + tig]       = pack2(acc[mt][nt][0], acc[mt][nt][1]);
                Ap[(r + 8) * 16 + nt * 4 + tig] = pack2(acc[mt][nt][2], acc[mt][nt][3]);
            }
        }
    }
}

// ---------------- kernel 2: C[16384,128] = A @ W via fp16 m16n8k16 ----------------
#define KC2 16   // uint (half2) columns per iteration = 32 k-values

__global__ __launch_bounds__(256, 1) void gemm_kernel(
    const float* __restrict__ bias, float* __restrict__ out)
{
    __shared__ unsigned Asu[2][128][20];
    __shared__ unsigned Bsu[2][16][132];
    __shared__ float s_bias[COUT];

    const int t = threadIdx.x;
    const int p0 = blockIdx.x * 128;
    const int bb = p0 >> 11;
    const int n0 = p0 & (NN - 1);

    if (t < COUT) s_bias[t] = bias[t];

    const int arow = t >> 1, ac = (t & 1) * 8;
    const int brow = t >> 4, bc = (t & 15) * 8;

    const int lane = t & 31;
    const int wid  = t >> 5;
    const int grp  = lane >> 2;
    const int tig  = lane & 3;
    const int wm = (wid >> 1) * 32;
    const int wn = (wid & 1) * 64;

    const unsigned* Ag = reinterpret_cast<const unsigned*>(g_Ah);
    uint4 ra0, ra1, rb0, rb1;

    auto ldg = [&](int k2c) {
        const unsigned* ap = Ag + (size_t)(p0 + arow) * KD2 + k2c + ac;
        ra0 = *reinterpret_cast<const uint4*>(ap);
        ra1 = *reinterpret_cast<const uint4*>(ap + 4);
        const unsigned* bp = g_cwP + (size_t)(k2c + brow) * COUT + bc;
        rb0 = *reinterpret_cast<const uint4*>(bp);
        rb1 = *reinterpret_cast<const uint4*>(bp + 4);
    };
    auto sts = [&](int buf) {
        *reinterpret_cast<uint4*>(&Asu[buf][arow][ac])     = ra0;
        *reinterpret_cast<uint4*>(&Asu[buf][arow][ac + 4]) = ra1;
        *reinterpret_cast<uint4*>(&Bsu[buf][brow][bc])     = rb0;
        *reinterpret_cast<uint4*>(&Bsu[buf][brow][bc + 4]) = rb1;
    };

    float c[2][8][4];
    #pragma unroll
    for (int ma = 0; ma < 2; ma++)
        #pragma unroll
        for (int nb = 0; nb < 8; nb++)
            #pragma unroll
            for (int r = 0; r < 4; r++) c[ma][nb][r] = 0.f;

    ldg(0);
    sts(0);
    __syncthreads();

    const int NIT = KD2 / KC2;   // 128
    for (int kt = 0; kt < NIT; kt++) {
        const int cur = kt & 1;
        if (kt + 1 < NIT) ldg((kt + 1) * KC2);

        #pragma unroll
        for (int ks = 0; ks < 2; ks++) {
            const int kb = ks * 8;
            unsigned a[2][4];
            #pragma unroll
            for (int ma = 0; ma < 2; ma++) {
                const int mbase = wm + ma * 16;
                a[ma][0] = Asu[cur][mbase + grp][kb + tig];
                a[ma][1] = Asu[cur][mbase + grp + 8][kb + tig];
                a[ma][2] = Asu[cur][mbase + grp][kb + tig + 4];
                a[ma][3] = Asu[cur][mbase + grp + 8][kb + tig + 4];
            }
            #pragma unroll
            for (int nb = 0; nb < 8; nb++) {
                unsigned b0 = Bsu[cur][kb + tig][wn + nb * 8 + grp];
                unsigned b1 = Bsu[cur][kb + tig + 4][wn + nb * 8 + grp];
                #pragma unroll
                for (int ma = 0; ma < 2; ma++)
                    mma_f16(c[ma][nb][0], c[ma][nb][1], c[ma][nb][2], c[ma][nb][3],
                            a[ma][0], a[ma][1], a[ma][2], a[ma][3], b0, b1);
            }
        }
        if (kt + 1 < NIT) sts(cur ^ 1);
        __syncthreads();
    }

    float* ob = out + (size_t)bb * COUT * NN;
    #pragma unroll
    for (int ma = 0; ma < 2; ma++) {
        const int m0 = wm + ma * 16 + grp;
        #pragma unroll
        for (int nb = 0; nb < 8; nb++) {
            const int col0 = wn + nb * 8 + tig * 2;
            const float bv0 = s_bias[col0], bv1 = s_bias[col0 + 1];
            ob[(size_t)col0       * NN + n0 + m0]     = c[ma][nb][0] + bv0;
            ob[(size_t)(col0 + 1) * NN + n0 + m0]     = c[ma][nb][1] + bv1;
            ob[(size_t)col0       * NN + n0 + m0 + 8] = c[ma][nb][2] + bv0;
            ob[(size_t)(col0 + 1) * NN + n0 + m0 + 8] = c[ma][nb][3] + bv1;
        }
    }
}

// ---------------- launch ----------------
extern "C" void kernel_launch(void* const* d_in, const int* in_sizes, int n_in,
                              void* d_out, int out_size) {
    const float* x       = (const float*)d_in[0];
    const float* feature = (const float*)d_in[1];
    const int*   nidx    = (const int*)  d_in[2];
    const float* Brff    = (const float*)d_in[3];
    const float* kern    = (const float*)d_in[4];
    const float* mw      = (const float*)d_in[5];
    const float* mb      = (const float*)d_in[6];
    const float* cw      = (const float*)d_in[7];
    const float* cb      = (const float*)d_in[8];
    float* out = (float*)d_out;

    prep_kernel<<<1024, 256>>>(x, feature, cw);
    point_kernel<<<NPTS, 128>>>(nidx, Brff, kern, mw, mb);
    gemm_kernel<<<NPTS / 128, 256>>>(cb, out);
}

// round 6
// speedup vs baseline: 1.1391x; 1.1391x over previous
#include <cuda_runtime.h>
#include <cuda_fp16.h>
#include <cstdint>

// ---------------- problem constants ----------------
#define BB 8
#define NN 2048
#define CIN 64
#define NK 32
#define KDIM 4096
#define KD2  (KDIM/2)
#define NPTS (BB*NN)
#define COUT 128
#define TWO_PI 6.283185307179586f

// ---------------- device scratch (static, no allocs) ----------------
__device__ __half   g_Ah[(size_t)NPTS * KDIM];      // 128 MB, [p][k] fp16, k-pairs packed
__device__ float    g_featT[(size_t)BB * NN * CIN]; // feature transposed [b][n][c]
__device__ float    g_xT[(size_t)BB * NN * 3];      // coords transposed [b][n][d]
__device__ unsigned g_cwP[(size_t)KD2 * COUT];      // [k2][o] half2(w[o][2k2], w[o][2k2+1])
__device__ unsigned g_mwF[128 * 16];                // per-thread mma A-fragments of mw

__device__ __forceinline__ unsigned pack2(float lo, float hi) {
    __half2 h = __floats2half2_rn(lo, hi);
    return *reinterpret_cast<unsigned*>(&h);
}

// m16n8k16 fp16 mma, f32 accumulate
__device__ __forceinline__ void mma_f16(float& c0, float& c1, float& c2, float& c3,
                                        unsigned a0, unsigned a1, unsigned a2, unsigned a3,
                                        unsigned b0, unsigned b1) {
    asm volatile(
        "mma.sync.aligned.m16n8k16.row.col.f32.f16.f16.f32 "
        "{%0,%1,%2,%3},{%4,%5,%6,%7},{%8,%9},{%0,%1,%2,%3};"
        : "+f"(c0), "+f"(c1), "+f"(c2), "+f"(c3)
        : "r"(a0), "r"(a1), "r"(a2), "r"(a3), "r"(b0), "r"(b1));
}

// ---------------- kernel 0: transposes + weight packing + mw fragments ----------------
__global__ void prep_kernel(const float* __restrict__ x,
                            const float* __restrict__ feat,
                            const float* __restrict__ cw,
                            const float* __restrict__ mw) {
    const int stride = gridDim.x * blockDim.x;
    const int tid = blockIdx.x * blockDim.x + threadIdx.x;

    // pre-pack mma A-fragments of mw for each of the 128 point-kernel threads
    for (int e = tid; e < 128 * 4; e += stride) {
        int t = e >> 2, ks = e & 3;
        int w = t >> 5, lane = t & 31;
        int grp = lane >> 2, tig = lane & 3;
        int r0 = w * 16 + grp;
        int m0 = ks * 16 + 2 * tig;
        g_mwF[t * 16 + ks * 4 + 0] = pack2(mw[r0 * 64 + m0],           mw[r0 * 64 + m0 + 1]);
        g_mwF[t * 16 + ks * 4 + 1] = pack2(mw[(r0 + 8) * 64 + m0],     mw[(r0 + 8) * 64 + m0 + 1]);
        g_mwF[t * 16 + ks * 4 + 2] = pack2(mw[r0 * 64 + m0 + 8],       mw[r0 * 64 + m0 + 9]);
        g_mwF[t * 16 + ks * 4 + 3] = pack2(mw[(r0 + 8) * 64 + m0 + 8], mw[(r0 + 8) * 64 + m0 + 9]);
    }
    for (int e = tid; e < BB * CIN * NN; e += stride) {
        int b = e / (CIN * NN);
        int r = e - b * (CIN * NN);
        int c = r / NN;
        int n = r - c * NN;
        g_featT[((size_t)b * NN + n) * CIN + c] = feat[e];
    }
    for (int e = tid; e < BB * 3 * NN; e += stride) {
        int b = e / (3 * NN);
        int r = e - b * (3 * NN);
        int d = r / NN;
        int n = r - d * NN;
        g_xT[((size_t)b * NN + n) * 3 + d] = x[e];
    }
    for (int e = tid; e < COUT * KD2; e += stride) {
        int o  = e >> 11;
        int k2 = e & (KD2 - 1);
        float2 v = *reinterpret_cast<const float2*>(cw + (size_t)o * KDIM + 2 * k2);
        g_cwP[(size_t)k2 * COUT + o] = pack2(v.x, v.y);
    }
}

// ---------------- kernel 1: per-point fp16 tensor-core MLP + F@perm ----------------
__global__ __launch_bounds__(128, 8) void point_kernel(
    const int*   __restrict__ nidx,
    const float* __restrict__ Brff,   // [7,32]
    const float* __restrict__ kern,   // [3,32]
    const float* __restrict__ mb)     // [64]
{
    const int p = blockIdx.x;
    const int b = p >> 11;
    const int t = threadIdx.x;
    const int lane = t & 31;
    const int w = t >> 5;
    const int grp = lane >> 2;
    const int tig = lane & 3;

    __shared__ unsigned u_xf[32][36];  // [k][m2]: m pairs, m<32 sin, m>=32 cos
    __shared__ unsigned u_F[128][20];  // [shuffled ch][k2]
    __shared__ unsigned u_pT[32][20];  // [j][i2]: perm^T
    __shared__ float s_br[7][32];      // pre-scaled by 2*pi
    __shared__ float s_base[32];       // 2pi * (c0 . B[0:3,m])
    __shared__ float s_rel[32][3];
    __shared__ float s_dis[32];
    __shared__ int   s_idx[32];

    // ---- mw A-fragments: 4 coalesced LDG.128 per thread ----
    unsigned amw[4][4];
    {
        const unsigned* fp = g_mwF + t * 16;
        #pragma unroll
        for (int ks = 0; ks < 4; ks++) {
            uint4 v = *reinterpret_cast<const uint4*>(fp + ks * 4);
            amw[ks][0] = v.x; amw[ks][1] = v.y; amw[ks][2] = v.z; amw[ks][3] = v.w;
        }
    }
    const float bv0 = mb[w * 16 + grp];
    const float bv1 = mb[w * 16 + grp + 8];

    for (int e = t; e < 224; e += 128) s_br[e >> 5][e & 31] = Brff[e] * TWO_PI;
    if (t < 32) s_idx[t] = nidx[p * NK + t];
    __syncthreads();

    float cx = 0.f, cy = 0.f, cz = 0.f;
    if (t < 32) {
        const float* cp = g_xT + ((size_t)b * NN + s_idx[t]) * 3;
        cx = cp[0]; cy = cp[1]; cz = cp[2];
    }

    // feature gather -> u_F rows 0,1 mod 4 (shuffled), packed neighbor pairs
    #pragma unroll
    for (int it = 0; it < 8; it++) {
        int e = t + it * 128;
        int c = e & 63, k2 = e >> 6;
        float f0 = g_featT[((size_t)b * NN + s_idx[2 * k2])     * CIN + c];
        float f1 = g_featT[((size_t)b * NN + s_idx[2 * k2 + 1]) * CIN + c];
        u_F[(c & 31) * 4 + (c >> 5)][k2] = pack2(f0, f1);
    }

    if (t < 32) {
        float c0x = __shfl_sync(0xffffffffu, cx, 0);
        float c0y = __shfl_sync(0xffffffffu, cy, 0);
        float c0z = __shfl_sync(0xffffffffu, cz, 0);
        float rx = cx - c0x, ry = cy - c0y, rz = cz - c0z;
        s_rel[t][0] = rx; s_rel[t][1] = ry; s_rel[t][2] = rz;
        s_dis[t] = sqrtf(rx * rx + ry * ry + rz * rz);
        // per-point constant part of the RFF arg (s_br already staged pre-sync)
        s_base[t] = c0x * s_br[0][t] + c0y * s_br[1][t] + c0z * s_br[2][t];
    }
    __syncthreads();

    // ---- RFF: arg = base[m] + rel.B[3:6,m] + dis*B[6,m]  (radians), 4 FMA/arg ----
    #pragma unroll
    for (int it = 0; it < 4; it++) {
        int e = t + it * 128;
        int k = e >> 4, m2 = e & 15;
        float rx = s_rel[k][0], ry = s_rel[k][1], rz = s_rel[k][2], dd = s_dis[k];
        int m = 2 * m2;
        float t0 = s_base[m]   + rx * s_br[3][m]   + ry * s_br[4][m]
                 + rz * s_br[5][m]   + dd * s_br[6][m];
        float t1 = s_base[m+1] + rx * s_br[3][m+1] + ry * s_br[4][m+1]
                 + rz * s_br[5][m+1] + dd * s_br[6][m+1];
        float s0, cv0, s1, cv1;
        __sincosf(t0, &s0, &cv0);
        __sincosf(t1, &s1, &cv1);
        u_xf[k][m2]      = pack2(s0, s1);
        u_xf[k][16 + m2] = pack2(cv0, cv1);
    }

    // ---- perm + topkmax, one column per thread, 3 recompute passes ----
    if (t < 32) {
        const int j = t;
        const float kx = kern[j], ky = kern[32 + j], kz = kern[64 + j];
        float s1 = 0.f;
        #pragma unroll
        for (int i = 0; i < 32; i++) {
            float v = s_rel[i][0] * kx + s_rel[i][1] * ky + s_rel[i][2] * kz;
            if (i == 0 && j == 0) v += 1.0f;
            s1 += fmaxf(v, 0.f);
        }
        float r1 = 1.0f / (s1 + 1e-6f);
        float s2 = 0.f;
        #pragma unroll
        for (int i = 0; i < 32; i++) {
            float v = s_rel[i][0] * kx + s_rel[i][1] * ky + s_rel[i][2] * kz;
            if (i == 0 && j == 0) v += 1.0f;
            v = fmaxf(v, 0.f) * r1;
            s2 += v * v;
        }
        float r2 = 1.0f / (s2 + 1e-6f);
        #pragma unroll
        for (int i2 = 0; i2 < 16; i2++) {
            float w0, w1;
            {
                int i = 2 * i2;
                float v = s_rel[i][0] * kx + s_rel[i][1] * ky + s_rel[i][2] * kz;
                if (i == 0 && j == 0) v += 1.0f;
                v = fmaxf(v, 0.f) * r1;
                v = v * v * r2;
                w0 = (v > 0.1f) ? v : 0.0f;
            }
            {
                int i = 2 * i2 + 1;
                float v = s_rel[i][0] * kx + s_rel[i][1] * ky + s_rel[i][2] * kz;
                v = fmaxf(v, 0.f) * r1;
                v = v * v * r2;
                w1 = (v > 0.1f) ? v : 0.0f;
            }
            u_pT[j][i2] = pack2(w0, w1);
        }
    }
    __syncthreads();

    // ---- GEMM1: mlp out rows [16w,16w+16), bias in accumulator ----
    {
        float acc[4][4];
        #pragma unroll
        for (int nt = 0; nt < 4; nt++) {
            acc[nt][0] = bv0; acc[nt][1] = bv0;
            acc[nt][2] = bv1; acc[nt][3] = bv1;
        }
        #pragma unroll
        for (int ks = 0; ks < 4; ks++) {
            const int kb = ks * 8;
            #pragma unroll
            for (int nt = 0; nt < 4; nt++) {
                unsigned b0 = u_xf[nt * 8 + grp][kb + tig];
                unsigned b1 = u_xf[nt * 8 + grp][kb + tig + 4];
                mma_f16(acc[nt][0], acc[nt][1], acc[nt][2], acc[nt][3],
                        amw[ks][0], amw[ks][1], amw[ks][2], amw[ks][3], b0, b1);
            }
        }
        const int r0 = w * 16 + grp, r1 = r0 + 8;
        const int cs0 = (r0 & 31) * 4 + 2 + (r0 >> 5);
        const int cs1 = (r1 & 31) * 4 + 2 + (r1 >> 5);
        #pragma unroll
        for (int nt = 0; nt < 4; nt++) {
            u_F[cs0][nt * 4 + tig] = pack2(acc[nt][0], acc[nt][1]);
            u_F[cs1][nt * 4 + tig] = pack2(acc[nt][2], acc[nt][3]);
        }
    }
    __syncthreads();

    // ---- GEMM2: feats2 = F @ perm, rows [32w, 32w+32) ----
    {
        float acc[2][4][4];
        #pragma unroll
        for (int mt = 0; mt < 2; mt++)
            #pragma unroll
            for (int nt = 0; nt < 4; nt++)
                #pragma unroll
                for (int r = 0; r < 4; r++) acc[mt][nt][r] = 0.f;

        #pragma unroll
        for (int ks = 0; ks < 2; ks++) {
            const int kb = ks * 8;
            unsigned a[2][4];
            #pragma unroll
            for (int mt = 0; mt < 2; mt++) {
                const int rb = w * 32 + mt * 16;
                a[mt][0] = u_F[rb + grp][kb + tig];
                a[mt][1] = u_F[rb + grp + 8][kb + tig];
                a[mt][2] = u_F[rb + grp][kb + tig + 4];
                a[mt][3] = u_F[rb + grp + 8][kb + tig + 4];
            }
            #pragma unroll
            for (int nt = 0; nt < 4; nt++) {
                unsigned b0 = u_pT[nt * 8 + grp][kb + tig];
                unsigned b1 = u_pT[nt * 8 + grp][kb + tig + 4];
                #pragma unroll
                for (int mt = 0; mt < 2; mt++)
                    mma_f16(acc[mt][nt][0], acc[mt][nt][1], acc[mt][nt][2], acc[mt][nt][3],
                            a[mt][0], a[mt][1], a[mt][2], a[mt][3], b0, b1);
            }
        }

        unsigned* Ap = reinterpret_cast<unsigned*>(g_Ah + (size_t)p * KDIM);
        #pragma unroll
        for (int mt = 0; mt < 2; mt++) {
            const int r = w * 32 + mt * 16 + grp;
            #pragma unroll
            for (int nt = 0; nt < 4; nt++) {
                Ap[r * 16 + nt * 4 + tig]       = pack2(acc[mt][nt][0], acc[mt][nt][1]);
                Ap[(r + 8) * 16 + nt * 4 + tig] = pack2(acc[mt][nt][2], acc[mt][nt][3]);
            }
        }
    }
}

// ---------------- kernel 2: C[16384,128] = A @ W via fp16 m16n8k16 ----------------
#define KC2 16   // uint (half2) columns per iteration = 32 k-values

__global__ __launch_bounds__(256, 1) void gemm_kernel(
    const float* __restrict__ bias, float* __restrict__ out)
{
    __shared__ unsigned Asu[2][128][20];
    __shared__ unsigned Bsu[2][16][132];
    __shared__ float s_bias[COUT];

    const int t = threadIdx.x;
    const int p0 = blockIdx.x * 128;
    const int bb = p0 >> 11;
    const int n0 = p0 & (NN - 1);

    if (t < COUT) s_bias[t] = bias[t];

    const int arow = t >> 1, ac = (t & 1) * 8;
    const int brow = t >> 4, bc = (t & 15) * 8;

    const int lane = t & 31;
    const int wid  = t >> 5;
    const int grp  = lane >> 2;
    const int tig  = lane & 3;
    const int wm = (wid >> 1) * 32;
    const int wn = (wid & 1) * 64;

    const unsigned* Ag = reinterpret_cast<const unsigned*>(g_Ah);
    uint4 ra0, ra1, rb0, rb1;

    auto ldg = [&](int k2c) {
        const unsigned* ap = Ag + (size_t)(p0 + arow) * KD2 + k2c + ac;
        ra0 = *reinterpret_cast<const uint4*>(ap);
        ra1 = *reinterpret_cast<const uint4*>(ap + 4);
        const unsigned* bp = g_cwP + (size_t)(k2c + brow) * COUT + bc;
        rb0 = *reinterpret_cast<const uint4*>(bp);
        rb1 = *reinterpret_cast<const uint4*>(bp + 4);
    };
    auto sts = [&](int buf) {
        *reinterpret_cast<uint4*>(&Asu[buf][arow][ac])     = ra0;
        *reinterpret_cast<uint4*>(&Asu[buf][arow][ac + 4]) = ra1;
        *reinterpret_cast<uint4*>(&Bsu[buf][brow][bc])     = rb0;
        *reinterpret_cast<uint4*>(&Bsu[buf][brow][bc + 4]) = rb1;
    };

    float c[2][8][4];
    #pragma unroll
    for (int ma = 0; ma < 2; ma++)
        #pragma unroll
        for (int nb = 0; nb < 8; nb++)
            #pragma unroll
            for (int r = 0; r < 4; r++) c[ma][nb][r] = 0.f;

    ldg(0);
    sts(0);
    __syncthreads();

    const int NIT = KD2 / KC2;   // 128
    for (int kt = 0; kt < NIT; kt++) {
        const int cur = kt & 1;
        if (kt + 1 < NIT) ldg((kt + 1) * KC2);

        #pragma unroll
        for (int ks = 0; ks < 2; ks++) {
            const int kb = ks * 8;
            unsigned a[2][4];
            #pragma unroll
            for (int ma = 0; ma < 2; ma++) {
                const int mbase = wm + ma * 16;
                a[ma][0] = Asu[cur][mbase + grp][kb + tig];
                a[ma][1] = Asu[cur][mbase + grp + 8][kb + tig];
                a[ma][2] = Asu[cur][mbase + grp][kb + tig + 4];
                a[ma][3] = Asu[cur][mbase + grp + 8][kb + tig + 4];
            }
            #pragma unroll
            for (int nb = 0; nb < 8; nb++) {
                unsigned b0 = Bsu[cur][kb + tig][wn + nb * 8 + grp];
                unsigned b1 = Bsu[cur][kb + tig + 4][wn + nb * 8 + grp];
                #pragma unroll
                for (int ma = 0; ma < 2; ma++)
                    mma_f16(c[ma][nb][0], c[ma][nb][1], c[ma][nb][2], c[ma][nb][3],
                            a[ma][0], a[ma][1], a[ma][2], a[ma][3], b0, b1);
            }
        }
        if (kt + 1 < NIT) sts(cur ^ 1);
        __syncthreads();
    }

    float* ob = out + (size_t)bb * COUT * NN;
    #pragma unroll
    for (int ma = 0; ma < 2; ma++) {
        const int m0 = wm + ma * 16 + grp;
        #pragma unroll
        for (int nb = 0; nb < 8; nb++) {
            const int col0 = wn + nb * 8 + tig * 2;
            const float bv0 = s_bias[col0], bv1 = s_bias[col0 + 1];
            ob[(size_t)col0       * NN + n0 + m0]     = c[ma][nb][0] + bv0;
            ob[(size_t)(col0 + 1) * NN + n0 + m0]     = c[ma][nb][1] + bv1;
            ob[(size_t)col0       * NN + n0 + m0 + 8] = c[ma][nb][2] + bv0;
            ob[(size_t)(col0 + 1) * NN + n0 + m0 + 8] = c[ma][nb][3] + bv1;
        }
    }
}

// ---------------- launch ----------------
extern "C" void kernel_launch(void* const* d_in, const int* in_sizes, int n_in,
                              void* d_out, int out_size) {
    const float* x       = (const float*)d_in[0];
    const float* feature = (const float*)d_in[1];
    const int*   nidx    = (const int*)  d_in[2];
    const float* Brff    = (const float*)d_in[3];
    const float* kern    = (const float*)d_in[4];
    const float* mw      = (const float*)d_in[5];
    const float* mb      = (const float*)d_in[6];
    const float* cw      = (const float*)d_in[7];
    const float* cb      = (const float*)d_in[8];
    float* out = (float*)d_out;

    prep_kernel<<<1024, 256>>>(x, feature, cw, mw);
    point_kernel<<<NPTS, 128>>>(nidx, Brff, kern, mb);
    gemm_kernel<<<NPTS / 128, 256>>>(cb, out);
}

// round 7
// speedup vs baseline: 1.4074x; 1.2355x over previous
#include <cuda_runtime.h>
#include <cuda_fp16.h>
#include <cstdint>

// ---------------- problem constants ----------------
#define BB 8
#define NN 2048
#define CIN 64
#define NK 32
#define KDIM 4096
#define KD2  (KDIM/2)
#define NPTS (BB*NN)
#define COUT 128
#define TWO_PI 6.283185307179586f

// ---------------- device scratch (static, no allocs) ----------------
__device__ __half   g_Ah[(size_t)NPTS * KDIM];      // [p][k] fp16
__device__ float    g_featT[(size_t)BB * NN * CIN]; // feature transposed [b][n][c]
__device__ float    g_xT[(size_t)BB * NN * 3];      // coords transposed [b][n][d]
__device__ unsigned g_cwP[(size_t)COUT * KD2];      // [o][k2] half2(w[o][2k2], w[o][2k2+1])
__device__ unsigned g_mwF[128 * 16];                // per-thread mma A-fragments of mw

__device__ __forceinline__ unsigned pack2(float lo, float hi) {
    __half2 h = __floats2half2_rn(lo, hi);
    return *reinterpret_cast<unsigned*>(&h);
}

// m16n8k16 fp16 mma, f32 accumulate
__device__ __forceinline__ void mma_f16(float& c0, float& c1, float& c2, float& c3,
                                        unsigned a0, unsigned a1, unsigned a2, unsigned a3,
                                        unsigned b0, unsigned b1) {
    asm volatile(
        "mma.sync.aligned.m16n8k16.row.col.f32.f16.f16.f32 "
        "{%0,%1,%2,%3},{%4,%5,%6,%7},{%8,%9},{%0,%1,%2,%3};"
        : "+f"(c0), "+f"(c1), "+f"(c2), "+f"(c3)
        : "r"(a0), "r"(a1), "r"(a2), "r"(a3), "r"(b0), "r"(b1));
}

__device__ __forceinline__ uint32_t smem_u32(const void* p) {
    uint32_t a;
    asm("{ .reg .u64 t; cvta.to.shared.u64 t, %1; cvt.u32.u64 %0, t; }" : "=r"(a) : "l"(p));
    return a;
}
__device__ __forceinline__ void cp16(uint32_t s, const void* g) {
    asm volatile("cp.async.cg.shared.global [%0], [%1], 16;" :: "r"(s), "l"(g));
}
__device__ __forceinline__ void cp_commit() {
    asm volatile("cp.async.commit_group;" ::: "memory");
}
template <int N>
__device__ __forceinline__ void cp_wait() {
    asm volatile("cp.async.wait_group %0;" :: "n"(N) : "memory");
}
__device__ __forceinline__ void ldsm4(unsigned& r0, unsigned& r1, unsigned& r2, unsigned& r3,
                                      uint32_t addr) {
    asm volatile("ldmatrix.sync.aligned.m8n8.x4.shared.b16 {%0,%1,%2,%3}, [%4];"
                 : "=r"(r0), "=r"(r1), "=r"(r2), "=r"(r3) : "r"(addr));
}

// ---------------- kernel 0: transposes + weight packing + mw fragments ----------------
__global__ void prep_kernel(const float* __restrict__ x,
                            const float* __restrict__ feat,
                            const float* __restrict__ cw,
                            const float* __restrict__ mw) {
    const int stride = gridDim.x * blockDim.x;
    const int tid = blockIdx.x * blockDim.x + threadIdx.x;

    for (int e = tid; e < 128 * 4; e += stride) {
        int t = e >> 2, ks = e & 3;
        int w = t >> 5, lane = t & 31;
        int grp = lane >> 2, tig = lane & 3;
        int r0 = w * 16 + grp;
        int m0 = ks * 16 + 2 * tig;
        g_mwF[t * 16 + ks * 4 + 0] = pack2(mw[r0 * 64 + m0],           mw[r0 * 64 + m0 + 1]);
        g_mwF[t * 16 + ks * 4 + 1] = pack2(mw[(r0 + 8) * 64 + m0],     mw[(r0 + 8) * 64 + m0 + 1]);
        g_mwF[t * 16 + ks * 4 + 2] = pack2(mw[r0 * 64 + m0 + 8],       mw[r0 * 64 + m0 + 9]);
        g_mwF[t * 16 + ks * 4 + 3] = pack2(mw[(r0 + 8) * 64 + m0 + 8], mw[(r0 + 8) * 64 + m0 + 9]);
    }
    for (int e = tid; e < BB * CIN * NN; e += stride) {
        int b = e / (CIN * NN);
        int r = e - b * (CIN * NN);
        int c = r / NN;
        int n = r - c * NN;
        g_featT[((size_t)b * NN + n) * CIN + c] = feat[e];
    }
    for (int e = tid; e < BB * 3 * NN; e += stride) {
        int b = e / (3 * NN);
        int r = e - b * (3 * NN);
        int d = r / NN;
        int n = r - d * NN;
        g_xT[((size_t)b * NN + n) * 3 + d] = x[e];
    }
    // conv_w -> g_cwP[o][k2], k packed in half2 (row-major: same linear order)
    for (int e = tid; e < COUT * KD2; e += stride)
        g_cwP[e] = pack2(cw[2 * e], cw[2 * e + 1]);
}

// ---------------- kernel 1: per-point fp16 tensor-core MLP + F@perm (round-6 best) ----
__global__ __launch_bounds__(128, 8) void point_kernel(
    const int*   __restrict__ nidx,
    const float* __restrict__ Brff,   // [7,32]
    const float* __restrict__ kern,   // [3,32]
    const float* __restrict__ mb)     // [64]
{
    const int p = blockIdx.x;
    const int b = p >> 11;
    const int t = threadIdx.x;
    const int lane = t & 31;
    const int w = t >> 5;
    const int grp = lane >> 2;
    const int tig = lane & 3;

    __shared__ unsigned u_xf[32][36];
    __shared__ unsigned u_F[128][20];
    __shared__ unsigned u_pT[32][20];
    __shared__ float s_br[7][32];
    __shared__ float s_base[32];
    __shared__ float s_rel[32][3];
    __shared__ float s_dis[32];
    __shared__ int   s_idx[32];

    unsigned amw[4][4];
    {
        const unsigned* fp = g_mwF + t * 16;
        #pragma unroll
        for (int ks = 0; ks < 4; ks++) {
            uint4 v = *reinterpret_cast<const uint4*>(fp + ks * 4);
            amw[ks][0] = v.x; amw[ks][1] = v.y; amw[ks][2] = v.z; amw[ks][3] = v.w;
        }
    }
    const float bv0 = mb[w * 16 + grp];
    const float bv1 = mb[w * 16 + grp + 8];

    for (int e = t; e < 224; e += 128) s_br[e >> 5][e & 31] = Brff[e] * TWO_PI;
    if (t < 32) s_idx[t] = nidx[p * NK + t];
    __syncthreads();

    float cx = 0.f, cy = 0.f, cz = 0.f;
    if (t < 32) {
        const float* cp = g_xT + ((size_t)b * NN + s_idx[t]) * 3;
        cx = cp[0]; cy = cp[1]; cz = cp[2];
    }

    #pragma unroll
    for (int it = 0; it < 8; it++) {
        int e = t + it * 128;
        int c = e & 63, k2 = e >> 6;
        float f0 = g_featT[((size_t)b * NN + s_idx[2 * k2])     * CIN + c];
        float f1 = g_featT[((size_t)b * NN + s_idx[2 * k2 + 1]) * CIN + c];
        u_F[(c & 31) * 4 + (c >> 5)][k2] = pack2(f0, f1);
    }

    if (t < 32) {
        float c0x = __shfl_sync(0xffffffffu, cx, 0);
        float c0y = __shfl_sync(0xffffffffu, cy, 0);
        float c0z = __shfl_sync(0xffffffffu, cz, 0);
        float rx = cx - c0x, ry = cy - c0y, rz = cz - c0z;
        s_rel[t][0] = rx; s_rel[t][1] = ry; s_rel[t][2] = rz;
        s_dis[t] = sqrtf(rx * rx + ry * ry + rz * rz);
        s_base[t] = c0x * s_br[0][t] + c0y * s_br[1][t] + c0z * s_br[2][t];
    }
    __syncthreads();

    #pragma unroll
    for (int it = 0; it < 4; it++) {
        int e = t + it * 128;
        int k = e >> 4, m2 = e & 15;
        float rx = s_rel[k][0], ry = s_rel[k][1], rz = s_rel[k][2], dd = s_dis[k];
        int m = 2 * m2;
        float t0 = s_base[m]   + rx * s_br[3][m]   + ry * s_br[4][m]
                 + rz * s_br[5][m]   + dd * s_br[6][m];
        float t1 = s_base[m+1] + rx * s_br[3][m+1] + ry * s_br[4][m+1]
                 + rz * s_br[5][m+1] + dd * s_br[6][m+1];
        float s0, cv0, s1, cv1;
        __sincosf(t0, &s0, &cv0);
        __sincosf(t1, &s1, &cv1);
        u_xf[k][m2]      = pack2(s0, s1);
        u_xf[k][16 + m2] = pack2(cv0, cv1);
    }

    if (t < 32) {
        const int j = t;
        const float kx = kern[j], ky = kern[32 + j], kz = kern[64 + j];
        float s1 = 0.f;
        #pragma unroll
        for (int i = 0; i < 32; i++) {
            float v = s_rel[i][0] * kx + s_rel[i][1] * ky + s_rel[i][2] * kz;
            if (i == 0 && j == 0) v += 1.0f;
            s1 += fmaxf(v, 0.f);
        }
        float r1 = 1.0f / (s1 + 1e-6f);
        float s2 = 0.f;
        #pragma unroll
        for (int i = 0; i < 32; i++) {
            float v = s_rel[i][0] * kx + s_rel[i][1] * ky + s_rel[i][2] * kz;
            if (i == 0 && j == 0) v += 1.0f;
            v = fmaxf(v, 0.f) * r1;
            s2 += v * v;
        }
        float r2 = 1.0f / (s2 + 1e-6f);
        #pragma unroll
        for (int i2 = 0; i2 < 16; i2++) {
            float w0, w1;
            {
                int i = 2 * i2;
                float v = s_rel[i][0] * kx + s_rel[i][1] * ky + s_rel[i][2] * kz;
                if (i == 0 && j == 0) v += 1.0f;
                v = fmaxf(v, 0.f) * r1;
                v = v * v * r2;
                w0 = (v > 0.1f) ? v : 0.0f;
            }
            {
                int i = 2 * i2 + 1;
                float v = s_rel[i][0] * kx + s_rel[i][1] * ky + s_rel[i][2] * kz;
                v = fmaxf(v, 0.f) * r1;
                v = v * v * r2;
                w1 = (v > 0.1f) ? v : 0.0f;
            }
            u_pT[j][i2] = pack2(w0, w1);
        }
    }
    __syncthreads();

    {
        float acc[4][4];
        #pragma unroll
        for (int nt = 0; nt < 4; nt++) {
            acc[nt][0] = bv0; acc[nt][1] = bv0;
            acc[nt][2] = bv1; acc[nt][3] = bv1;
        }
        #pragma unroll
        for (int ks = 0; ks < 4; ks++) {
            const int kb = ks * 8;
            #pragma unroll
            for (int nt = 0; nt < 4; nt++) {
                unsigned b0 = u_xf[nt * 8 + grp][kb + tig];
                unsigned b1 = u_xf[nt * 8 + grp][kb + tig + 4];
                mma_f16(acc[nt][0], acc[nt][1], acc[nt][2], acc[nt][3],
                        amw[ks][0], amw[ks][1], amw[ks][2], amw[ks][3], b0, b1);
            }
        }
        const int r0 = w * 16 + grp, r1 = r0 + 8;
        const int cs0 = (r0 & 31) * 4 + 2 + (r0 >> 5);
        const int cs1 = (r1 & 31) * 4 + 2 + (r1 >> 5);
        #pragma unroll
        for (int nt = 0; nt < 4; nt++) {
            u_F[cs0][nt * 4 + tig] = pack2(acc[nt][0], acc[nt][1]);
            u_F[cs1][nt * 4 + tig] = pack2(acc[nt][2], acc[nt][3]);
        }
    }
    __syncthreads();

    {
        float acc[2][4][4];
        #pragma unroll
        for (int mt = 0; mt < 2; mt++)
            #pragma unroll
            for (int nt = 0; nt < 4; nt++)
                #pragma unroll
                for (int r = 0; r < 4; r++) acc[mt][nt][r] = 0.f;

        #pragma unroll
        for (int ks = 0; ks < 2; ks++) {
            const int kb = ks * 8;
            unsigned a[2][4];
            #pragma unroll
            for (int mt = 0; mt < 2; mt++) {
                const int rb = w * 32 + mt * 16;
                a[mt][0] = u_F[rb + grp][kb + tig];
                a[mt][1] = u_F[rb + grp + 8][kb + tig];
                a[mt][2] = u_F[rb + grp][kb + tig + 4];
                a[mt][3] = u_F[rb + grp + 8][kb + tig + 4];
            }
            #pragma unroll
            for (int nt = 0; nt < 4; nt++) {
                unsigned b0 = u_pT[nt * 8 + grp][kb + tig];
                unsigned b1 = u_pT[nt * 8 + grp][kb + tig + 4];
                #pragma unroll
                for (int mt = 0; mt < 2; mt++)
                    mma_f16(acc[mt][nt][0], acc[mt][nt][1], acc[mt][nt][2], acc[mt][nt][3],
                            a[mt][0], a[mt][1], a[mt][2], a[mt][3], b0, b1);
            }
        }

        unsigned* Ap = reinterpret_cast<unsigned*>(g_Ah + (size_t)p * KDIM);
        #pragma unroll
        for (int mt = 0; mt < 2; mt++) {
            const int r = w * 32 + mt * 16 + grp;
            #pragma unroll
            for (int nt = 0; nt < 4; nt++) {
                Ap[r * 16 + nt * 4 + tig]       = pack2(acc[mt][nt][0], acc[mt][nt][1]);
                Ap[(r + 8) * 16 + nt * 4 + tig] = pack2(acc[mt][nt][2], acc[mt][nt][3]);
            }
        }
    }
}

// ---------------- kernel 2: cp.async 3-stage + ldmatrix fp16 GEMM ----------------
// C[16384,128] = A[.,4096] @ W[128,4096]^T. CTA: 128m x 128n, 128 iters of 32k.
#define ROW_U 20                  // uints per smem row (16 data + 4 pad) = 80B
#define A_OFF_U 0
#define B_OFF_U (128 * ROW_U)     // 2560
#define STAGE_U (2 * 128 * ROW_U) // 5120 uints = 20480 B
#define NSTAGE 3
#define G_SMEM (NSTAGE * STAGE_U * 4)   // 61440 B
#define NIT 128

__global__ __launch_bounds__(256, 1) void gemm_kernel(
    const float* __restrict__ bias, float* __restrict__ out)
{
    extern __shared__ unsigned sm[];
    __shared__ float s_bias[COUT];

    const int t = threadIdx.x;
    const int p0 = blockIdx.x * 128;
    const int bb = p0 >> 11;
    const int n0 = p0 & (NN - 1);

    if (t < COUT) s_bias[t] = bias[t];

    const int lane = t & 31;
    const int wid  = t >> 5;
    const int grp  = lane >> 2;
    const int tig  = lane & 3;
    const int wm = (wid >> 1) * 32;
    const int wn = (wid & 1) * 64;

    const unsigned* Ag = reinterpret_cast<const unsigned*>(g_Ah);
    const unsigned* Bg = g_cwP;
    const uint32_t smb = smem_u32(sm);

    // per-thread staging coords: 512 16B-chunks for A, 512 for B
    const int srow = t >> 2;          // 0..63 (+64)
    const int sch  = t & 3;           // 16B chunk 0..3

    auto issue = [&](int q, int slot) {
        const uint32_t sb = smb + slot * (STAGE_U * 4);
        #pragma unroll
        for (int i = 0; i < 2; i++) {
            int m = srow + 64 * i;
            cp16(sb + m * 80 + sch * 16,
                 Ag + (size_t)(p0 + m) * KD2 + q * 16 + sch * 4);
        }
        #pragma unroll
        for (int i = 0; i < 2; i++) {
            int o = srow + 64 * i;
            cp16(sb + B_OFF_U * 4 + o * 80 + sch * 16,
                 Bg + (size_t)o * KD2 + q * 16 + sch * 4);
        }
        cp_commit();
    };

    float c[2][8][4];
    #pragma unroll
    for (int ma = 0; ma < 2; ma++)
        #pragma unroll
        for (int nb = 0; nb < 8; nb++)
            #pragma unroll
            for (int r = 0; r < 4; r++) c[ma][nb][r] = 0.f;

    issue(0, 0);
    issue(1, 1);

    // ldmatrix per-lane address components
    const int lrow8 = lane & 7;
    const int lhi   = (lane >> 3) & 1;
    const int lcol  = (lane >> 4) & 1;

    int slot = 0;
    for (int i = 0; i < NIT; i++) {
        if (i < NIT - 1) cp_wait<1>(); else cp_wait<0>();
        __syncthreads();
        if (i + 2 < NIT) {
            int ns = slot + 2; if (ns >= NSTAGE) ns -= NSTAGE;
            issue(i + 2, ns);
        }

        const uint32_t ab = smb + slot * (STAGE_U * 4);
        const uint32_t bbod = ab + B_OFF_U * 4;

        // A fragments: [ks][ma][a0..a3]
        unsigned a[2][2][4];
        #pragma unroll
        for (int ks = 0; ks < 2; ks++)
            #pragma unroll
            for (int ma = 0; ma < 2; ma++) {
                int row = wm + ma * 16 + lrow8 + lhi * 8;
                uint32_t addr = ab + row * 80 + ks * 32 + lcol * 16;
                ldsm4(a[ks][ma][0], a[ks][ma][1], a[ks][ma][2], a[ks][ma][3], addr);
            }
        // B fragments: [nb][b0ks0, b1ks0, b0ks1, b1ks1]
        unsigned bf[8][4];
        {
            const int bcol = (lane >> 3) * 16;   // 16B chunk = k2 group
            #pragma unroll
            for (int nb = 0; nb < 8; nb++) {
                int row = wn + nb * 8 + lrow8;
                ldsm4(bf[nb][0], bf[nb][1], bf[nb][2], bf[nb][3],
                      bbod + row * 80 + bcol);
            }
        }
        #pragma unroll
        for (int ks = 0; ks < 2; ks++)
            #pragma unroll
            for (int nb = 0; nb < 8; nb++)
                #pragma unroll
                for (int ma = 0; ma < 2; ma++)
                    mma_f16(c[ma][nb][0], c[ma][nb][1], c[ma][nb][2], c[ma][nb][3],
                            a[ks][ma][0], a[ks][ma][1], a[ks][ma][2], a[ks][ma][3],
                            bf[nb][2 * ks], bf[nb][2 * ks + 1]);

        if (++slot >= NSTAGE) slot = 0;
        __syncthreads();
    }

    float* ob = out + (size_t)bb * COUT * NN;
    #pragma unroll
    for (int ma = 0; ma < 2; ma++) {
        const int m0 = wm + ma * 16 + grp;
        #pragma unroll
        for (int nb = 0; nb < 8; nb++) {
            const int col0 = wn + nb * 8 + tig * 2;
            const float bv0 = s_bias[col0], bv1 = s_bias[col0 + 1];
            ob[(size_t)col0       * NN + n0 + m0]     = c[ma][nb][0] + bv0;
            ob[(size_t)(col0 + 1) * NN + n0 + m0]     = c[ma][nb][1] + bv1;
            ob[(size_t)col0       * NN + n0 + m0 + 8] = c[ma][nb][2] + bv0;
            ob[(size_t)(col0 + 1) * NN + n0 + m0 + 8] = c[ma][nb][3] + bv1;
        }
    }
}

// ---------------- launch ----------------
extern "C" void kernel_launch(void* const* d_in, const int* in_sizes, int n_in,
                              void* d_out, int out_size) {
    const float* x       = (const float*)d_in[0];
    const float* feature = (const float*)d_in[1];
    const int*   nidx    = (const int*)  d_in[2];
    const float* Brff    = (const float*)d_in[3];
    const float* kern    = (const float*)d_in[4];
    const float* mw      = (const float*)d_in[5];
    const float* mb      = (const float*)d_in[6];
    const float* cw      = (const float*)d_in[7];
    const float* cb      = (const float*)d_in[8];
    float* out = (float*)d_out;

    cudaFuncSetAttribute(gemm_kernel,
                         cudaFuncAttributeMaxDynamicSharedMemorySize, G_SMEM);

    prep_kernel<<<1024, 256>>>(x, feature, cw, mw);
    point_kernel<<<NPTS, 128>>>(nidx, Brff, kern, mb);
    gemm_kernel<<<NPTS / 128, 256, G_SMEM>>>(cb, out);
}